// round 5
// baseline (speedup 1.0000x reference)
#include <cuda_runtime.h>
#include <math.h>

#define BATCH 4
#define NPTS  8192
#define TPB   256
#define PPT   4                         // query points per thread
#define PPB   (TPB * PPT)               // 1024 query points per block
#define PCHUNKS (NPTS / PPB)            // 8
#define OC    4                         // scan-chunk splits
#define CHUNK (NPTS / OC)               // 2048 scan points staged in smem
#define SLOTS (2 * BATCH * NPTS)        // 65536 (both directions)

// Partial squared-min per (oc, dir, b, i). Fully rewritten every launch -> no init.
__device__ float g_pmin[OC * SLOTS];

__device__ __forceinline__ unsigned long long pack2(float lo, float hi) {
    unsigned long long r;
    asm("mov.b64 %0, {%1, %2};" : "=l"(r) : "f"(lo), "f"(hi));
    return r;
}
__device__ __forceinline__ unsigned long long fma2(unsigned long long a,
                                                   unsigned long long b,
                                                   unsigned long long c) {
    unsigned long long d;
    asm("fma.rn.f32x2 %0, %1, %2, %3;" : "=l"(d) : "l"(a), "l"(b), "l"(c));
    return d;
}
__device__ __forceinline__ void unpack2(unsigned long long v, float& lo, float& hi) {
    asm("mov.b64 {%0, %1}, %2;" : "=f"(lo), "=f"(hi) : "l"(v));
}

__global__ void __launch_bounds__(TPB) chamfer_main(
    const float* __restrict__ pred, const float* __restrict__ gt)
{
    // Component-separated scan data so LDS.64 yields {c_j, c_j+1}.
    __shared__ float2 sgx2[CHUNK / 2], sgy2[CHUNK / 2], sgz2[CHUNK / 2], sgw2[CHUNK / 2];
    float* sgx = (float*)sgx2;
    float* sgy = (float*)sgy2;
    float* sgz = (float*)sgz2;
    float* sgw = (float*)sgw2;

    int bid = blockIdx.x;
    int oc   = bid % OC;       bid /= OC;
    int pcid = bid % PCHUNKS;  bid /= PCHUNKS;
    int b    = bid % BATCH;    bid /= BATCH;
    int dir  = bid;  // 0: query=pred scan=gt ; 1: query=gt scan=pred

    const float* Aq = (dir == 0 ? pred : gt) + (size_t)b * 3 * NPTS;
    const float* Bs = (dir == 0 ? gt : pred) + (size_t)b * 3 * NPTS;

    // Stage + transform one chunk of the scanned cloud (coalesced [3,N] reads)
    int jbase = oc * CHUNK;
    for (int idx = threadIdx.x; idx < CHUNK; idx += TPB) {
        float gx = Bs[jbase + idx];
        float gy = Bs[NPTS + jbase + idx];
        float gz = Bs[2 * NPTS + jbase + idx];
        sgx[idx] = -2.0f * gx;
        sgy[idx] = -2.0f * gy;
        sgz[idx] = -2.0f * gz;
        sgw[idx] = fmaf(gx, gx, fmaf(gy, gy, gz * gz));
    }
    __syncthreads();

    unsigned long long px2[PPT], py2[PPT], pz2[PPT];
    float psq[PPT], mnl[PPT], mnh[PPT];
    int i0 = pcid * PPB + threadIdx.x;
    #pragma unroll
    for (int p = 0; p < PPT; p++) {
        int i = i0 + p * TPB;
        float px = Aq[i];
        float py = Aq[NPTS + i];
        float pz = Aq[2 * NPTS + i];
        psq[p] = fmaf(px, px, fmaf(py, py, pz * pz));
        px2[p] = pack2(px, px);   // query duplicated once, outside the loop
        py2[p] = pack2(py, py);
        pz2[p] = pack2(pz, pz);
        mnl[p] = 3.0e38f;
        mnh[p] = 3.0e38f;
    }

    const unsigned long long* gx64 = (const unsigned long long*)sgx;
    const unsigned long long* gy64 = (const unsigned long long*)sgy;
    const unsigned long long* gz64 = (const unsigned long long*)sgz;
    const unsigned long long* gw64 = (const unsigned long long*)sgw;

    #pragma unroll 4
    for (int j2 = 0; j2 < CHUNK / 2; j2++) {
        unsigned long long gx2 = gx64[j2];   // LDS.64 broadcast: {gx_j, gx_j+1}
        unsigned long long gy2 = gy64[j2];
        unsigned long long gz2 = gz64[j2];
        unsigned long long gw2 = gw64[j2];
        #pragma unroll
        for (int p = 0; p < PPT; p++) {
            // acc = |g|^2 - 2 p.g   for two scan points at once
            unsigned long long acc = fma2(pz2[p], gz2, gw2);
            acc = fma2(py2[p], gy2, acc);
            acc = fma2(px2[p], gx2, acc);
            float lo, hi;
            unpack2(acc, lo, hi);
            mnl[p] = fminf(mnl[p], lo);
            mnh[p] = fminf(mnh[p], hi);
        }
    }

    float* out = g_pmin + (size_t)oc * SLOTS + (size_t)dir * BATCH * NPTS + (size_t)b * NPTS;
    #pragma unroll
    for (int p = 0; p < PPT; p++) {
        float d2 = fmaxf(psq[p] + fminf(mnl[p], mnh[p]), 0.0f);  // clamp cancellation
        out[i0 + p * TPB] = d2;
    }
}

// Single block: min over OC partials, sqrt, deterministic tree-sum.
__global__ void __launch_bounds__(1024) reduce_kernel(float* __restrict__ out) {
    __shared__ float ssum[1024];
    int tid = threadIdx.x;
    const float4* base = (const float4*)g_pmin;   // [OC][SLOTS/4] float4s
    const int Q = SLOTS / 4;                      // 16384
    float s = 0.0f;
    for (int k = tid; k < Q; k += 1024) {
        float4 a = base[k];
        float4 b = base[Q + k];
        float4 c = base[2 * Q + k];
        float4 d = base[3 * Q + k];
        float mx = fminf(fminf(a.x, b.x), fminf(c.x, d.x));
        float my = fminf(fminf(a.y, b.y), fminf(c.y, d.y));
        float mz = fminf(fminf(a.z, b.z), fminf(c.z, d.z));
        float mw = fminf(fminf(a.w, b.w), fminf(c.w, d.w));
        s += sqrtf(mx) + sqrtf(my) + sqrtf(mz) + sqrtf(mw);
    }
    ssum[tid] = s;
    __syncthreads();
    for (int off = 512; off > 0; off >>= 1) {
        if (tid < off) ssum[tid] += ssum[tid + off];
        __syncthreads();
    }
    if (tid == 0) out[0] = ssum[0] * (1.0f / (float)BATCH);
}

extern "C" void kernel_launch(void* const* d_in, const int* in_sizes, int n_in,
                              void* d_out, int out_size) {
    const float* pred = (const float*)d_in[0];
    const float* gt   = (const float*)d_in[1];
    float* out = (float*)d_out;
    (void)in_sizes; (void)n_in; (void)out_size;

    // grid: 2 dirs * 4 batches * 8 query-chunks * 4 scan-chunks = 256 blocks
    chamfer_main<<<2 * BATCH * PCHUNKS * OC, TPB>>>(pred, gt);
    reduce_kernel<<<1, 1024>>>(out);
}